// round 10
// baseline (speedup 1.0000x reference)
#include <cuda_runtime.h>
#include <cuda_fp16.h>

#define N_NODES     50000
#define N_EDGES     800000
#define HIDDEN      128
#define F_IN        11
#define NUM_CLASSES 19
#define NUM_GRAPHS  2048

#define SCAN_B      256
#define N_SBLK      ((N_NODES + SCAN_B - 1) / SCAN_B)   // 196

// ---- scratch ----
__device__ __align__(16) __half g_h16a[N_NODES * HIDDEN]; // layer-1 output
__device__ __align__(16) __half g_h16b[N_NODES * HIDDEN]; // layer-2 output
__device__ __align__(16) float g_h[N_NODES * HIDDEN];     // layer-3 output (fp32)
__device__ float g_dinv[N_NODES];
__device__ int   g_counts[N_NODES];
__device__ int   g_fill[N_NODES];
__device__ int   g_rowptr[N_NODES + 1];
__device__ unsigned long long g_desc[N_SBLK];             // lookback descriptors
__device__ __align__(16) int2 g_edge[N_EDGES];            // (col, norm bits)
__device__ __align__(16) float g_Wt2[HIDDEN * HIDDEN];
__device__ __align__(16) float g_Wt3[HIDDEN * HIDDEN];
__device__ int   g_gcnt[NUM_GRAPHS];
__device__ int   g_gstart[NUM_GRAPHS + 1];

__device__ __forceinline__ int clampi(int v, int hi) {
    return v < 0 ? 0 : (v >= hi ? hi - 1 : v);
}

__device__ __forceinline__ void fma_h2(float4& acc, uint2 v, float w) {
    float2 fa = __half22float2(*(const __half2*)&v.x);
    float2 fb = __half22float2(*(const __half2*)&v.y);
    acc.x += w * fa.x; acc.y += w * fa.y; acc.z += w * fb.x; acc.w += w * fb.y;
}

// ---------------------------------------------------------------------------
__global__ void k_zero() {
    int i = blockIdx.x * blockDim.x + threadIdx.x;
    if (i < N_NODES) { g_counts[i] = 0; g_fill[i] = 0; }
    if (i < NUM_GRAPHS) g_gcnt[i] = 0;
    if (i < N_SBLK) g_desc[i] = 0ULL;
}

__global__ void k_deg(const int* __restrict__ ei) {
    int e = blockIdx.x * blockDim.x + threadIdx.x;
    if (e < N_EDGES) atomicAdd(&g_counts[clampi(ei[N_EDGES + e], N_NODES)], 1);
}

// fused: dinv + per-graph node counts + W2/W3 transpose
__global__ void k_node_setup(const int* __restrict__ batch,
                             const float* __restrict__ W2,
                             const float* __restrict__ W3) {
    int i = blockIdx.x * blockDim.x + threadIdx.x;
    if (i < N_NODES) {
        g_dinv[i] = rsqrtf((float)g_counts[i] + 1.0f);
        atomicAdd(&g_gcnt[clampi(batch[i], NUM_GRAPHS)], 1);
    }
    if (i < HIDDEN * HIDDEN) {
        int k = i / HIDDEN, c = i % HIDDEN;
        g_Wt2[c * HIDDEN + k] = W2[i];
        g_Wt3[c * HIDDEN + k] = W3[i];
    }
}

// single-pass scan: blocks 0..N_SBLK-1 decoupled-lookback scan of g_counts
// -> g_rowptr; block N_SBLK scans g_gcnt -> g_gstart.
__global__ void __launch_bounds__(SCAN_B) k_scan_lb() {
    __shared__ int s[SCAN_B];
    __shared__ unsigned int s_excl;
    int b = blockIdx.x;
    int t = threadIdx.x;
    volatile unsigned long long* vdesc = g_desc;

    if (b < N_SBLK) {
        int i = b * SCAN_B + t;
        int c = (i < N_NODES) ? g_counts[i] : 0;
        s[t] = c;
        __syncthreads();
        for (int off = 1; off < SCAN_B; off <<= 1) {
            int v = (t >= off) ? s[t - off] : 0;
            __syncthreads();
            s[t] += v;
            __syncthreads();
        }
        unsigned int total = (unsigned int)s[SCAN_B - 1];

        if (t < 32) {   // warp 0: publish + lookback
            if (b == 0) {
                if (t == 0) {
                    __threadfence();
                    vdesc[0] = (2ULL << 62) | (unsigned long long)total;
                    s_excl = 0;
                }
            } else {
                if (t == 0) {
                    __threadfence();
                    vdesc[b] = (1ULL << 62) | (unsigned long long)total;
                }
                // warp-parallel lookback
                unsigned long long sum = 0;
                int base = b - 1;
                while (true) {
                    int idx = base - t;
                    unsigned long long d = (idx >= 0) ? vdesc[idx] : (2ULL << 62);
                    unsigned st = (unsigned)(d >> 62);
                    unsigned long long val = d & 0xffffffffULL;
                    unsigned pmask = __ballot_sync(0xffffffff, st == 2);
                    unsigned zmask = __ballot_sync(0xffffffff, st == 0);
                    if (pmask) {
                        int fp = __ffs(pmask) - 1;
                        if (zmask & ((fp ? ((1u << fp) - 1u) : 0u))) continue;
                        unsigned long long con = (t <= fp) ? val : 0ULL;
                        for (int off = 16; off; off >>= 1)
                            con += __shfl_down_sync(0xffffffff, con, off);
                        if (t == 0) sum += con;
                        break;
                    } else {
                        if (zmask) continue;
                        unsigned long long con = val;
                        for (int off = 16; off; off >>= 1)
                            con += __shfl_down_sync(0xffffffff, con, off);
                        if (t == 0) sum += con;
                        base -= 32;
                    }
                }
                if (t == 0) {
                    __threadfence();
                    vdesc[b] = (2ULL << 62) | ((sum + total) & 0xffffffffULL);
                    s_excl = (unsigned int)sum;
                }
            }
        }
        __syncthreads();
        unsigned int excl = s_excl;
        if (i < N_NODES) g_rowptr[i] = (int)(excl + (unsigned int)s[t] - (unsigned int)c);
        if (i == N_NODES - 1) g_rowptr[N_NODES] = N_EDGES;
    } else {
        // graph-offset scan: 2048 counts, 8 per thread
        int base = t * 8;
        int vals[8];
        int th_total = 0;
#pragma unroll
        for (int j = 0; j < 8; j++) { vals[j] = g_gcnt[base + j]; th_total += vals[j]; }
        s[t] = th_total;
        __syncthreads();
        for (int off = 1; off < SCAN_B; off <<= 1) {
            int v = (t >= off) ? s[t - off] : 0;
            __syncthreads();
            s[t] += v;
            __syncthreads();
        }
        int run = s[t] - th_total;
#pragma unroll
        for (int j = 0; j < 8; j++) { g_gstart[base + j] = run; run += vals[j]; }
        if (t == SCAN_B - 1) g_gstart[NUM_GRAPHS] = s[SCAN_B - 1];
    }
}

__global__ void k_scatter(const int* __restrict__ ei) {
    int e = blockIdx.x * blockDim.x + threadIdx.x;
    if (e >= N_EDGES) return;
    int s = clampi(ei[e], N_NODES);
    int d = clampi(ei[N_EDGES + e], N_NODES);
    int pos = g_rowptr[d] + atomicAdd(&g_fill[d], 1);
    g_edge[pos] = make_int2(s, __float_as_int(g_dinv[s] * g_dinv[d]));
}

// ---- fused layer 1: aggregate raw x (11-dim) into smem + GEMM -> fp16 h (a) ----
__global__ void __launch_bounds__(128) k_layer1(const float* __restrict__ x,
                                                const float* __restrict__ W1,
                                                const float* __restrict__ b1) {
    __shared__ float Ws[F_IN * HIDDEN];
    __shared__ float xs[32][12];
    int t = threadIdx.x;
    int node0 = blockIdx.x * 32;

    for (int i = t; i < F_IN * HIDDEN; i += 128) Ws[i] = W1[i];

    // agg phase: 352 items = 32 nodes x 11 features
    for (int item = t; item < 32 * F_IN; item += 128) {
        int r = item / F_IN, f = item % F_IN;
        int node = node0 + r;
        float acc = 0.0f;
        if (node < N_NODES) {
            int s = g_rowptr[node], e = g_rowptr[node + 1];
            int i = s;
            for (; i + 4 <= e; i += 4) {
                int2 e0 = g_edge[i], e1 = g_edge[i + 1], e2 = g_edge[i + 2], e3 = g_edge[i + 3];
                float x0 = x[e0.x * F_IN + f];
                float x1 = x[e1.x * F_IN + f];
                float x2 = x[e2.x * F_IN + f];
                float x3 = x[e3.x * F_IN + f];
                acc += x0 * __int_as_float(e0.y) + x1 * __int_as_float(e1.y)
                     + x2 * __int_as_float(e2.y) + x3 * __int_as_float(e3.y);
            }
            for (; i < e; i++) {
                int2 ed = g_edge[i];
                acc += x[ed.x * F_IN + f] * __int_as_float(ed.y);
            }
            float di = g_dinv[node];
            acc += x[node * F_IN + f] * (di * di);
        }
        xs[r][f] = acc;
    }
    __syncthreads();

    // gemm phase
    float bb = b1[t];
    for (int n = 0; n < 32; n++) {
        int node = node0 + n;
        if (node >= N_NODES) break;
        float acc = bb;
#pragma unroll
        for (int k = 0; k < F_IN; k++)
            acc += xs[n][k] * Ws[k * HIDDEN + t];
        g_h16a[node * HIDDEN + t] = __float2half(fmaxf(acc, 0.0f));
    }
}

// ---- fused layers 2/3: aggregate fp16 h into smem + FFMA2 GEMM ----
// which_w = 0: read g_h16a, W2^T, relu, write g_h16b
// which_w = 1: read g_h16b, W3^T, no relu, write fp32 g_h
__global__ void __launch_bounds__(256) k_layer23(const float* __restrict__ b, int which_w) {
    __shared__ __align__(16) float2 xs2[16][HIDDEN];   // 16 KB, (row2p, row2p+1) pairs
    const float* __restrict__ Wt = which_w ? g_Wt3 : g_Wt2;
    const uint2* __restrict__ h2 = which_w ? (const uint2*)g_h16b : (const uint2*)g_h16a;
    int t = threadIdx.x;
    int row0 = blockIdx.x * 32;
    int wid = t >> 5, lane = t & 31;

    // agg phase: 8 warps x 4 nodes, warp-per-node, lane owns 4 features
    for (int q = 0; q < 4; q++) {
        int nl = wid * 4 + q;
        int node = row0 + nl;
        float4 acc = make_float4(0.f, 0.f, 0.f, 0.f);
        if (node < N_NODES) {
            int s = g_rowptr[node], e = g_rowptr[node + 1];
            int i = s;
            for (; i + 4 <= e; i += 4) {
                int2 e0 = g_edge[i], e1 = g_edge[i + 1], e2 = g_edge[i + 2], e3 = g_edge[i + 3];
                uint2 v0 = h2[e0.x * 32 + lane];
                uint2 v1 = h2[e1.x * 32 + lane];
                uint2 v2 = h2[e2.x * 32 + lane];
                uint2 v3 = h2[e3.x * 32 + lane];
                fma_h2(acc, v0, __int_as_float(e0.y));
                fma_h2(acc, v1, __int_as_float(e1.y));
                fma_h2(acc, v2, __int_as_float(e2.y));
                fma_h2(acc, v3, __int_as_float(e3.y));
            }
            for (; i < e; i++) {
                int2 ed = g_edge[i];
                fma_h2(acc, h2[ed.x * 32 + lane], __int_as_float(ed.y));
            }
            float di = g_dinv[node];
            fma_h2(acc, h2[node * 32 + lane], di * di);
        }
        int p = nl >> 1, par = nl & 1;
        ((float*)&xs2[p][4 * lane + 0])[par] = acc.x;
        ((float*)&xs2[p][4 * lane + 1])[par] = acc.y;
        ((float*)&xs2[p][4 * lane + 2])[par] = acc.z;
        ((float*)&xs2[p][4 * lane + 3])[par] = acc.w;
    }
    __syncthreads();

    // gemm phase: col = t&127, group t>>7 handles 8 row-pairs
    int col = t & 127;
    int pbase = (t >> 7) * 8;
    unsigned long long acc[8];
    float bbf = b[col];
    unsigned long long bb2;
    asm("mov.b64 %0, {%1, %1};" : "=l"(bb2) : "f"(bbf));
#pragma unroll
    for (int p = 0; p < 8; p++) acc[p] = bb2;

    const float4* __restrict__ wt4 = (const float4*)(Wt + col * HIDDEN);
    for (int kk = 0; kk < 32; kk++) {
        float4 w = wt4[kk];
        unsigned long long w0, w1, w2, w3;
        asm("mov.b64 %0, {%1, %1};" : "=l"(w0) : "f"(w.x));
        asm("mov.b64 %0, {%1, %1};" : "=l"(w1) : "f"(w.y));
        asm("mov.b64 %0, {%1, %1};" : "=l"(w2) : "f"(w.z));
        asm("mov.b64 %0, {%1, %1};" : "=l"(w3) : "f"(w.w));
#pragma unroll
        for (int p = 0; p < 8; p++) {
            ulonglong2 xa = *(const ulonglong2*)&xs2[pbase + p][4 * kk];
            ulonglong2 xb = *(const ulonglong2*)&xs2[pbase + p][4 * kk + 2];
            asm("fma.rn.f32x2 %0, %1, %2, %0;" : "+l"(acc[p]) : "l"(xa.x), "l"(w0));
            asm("fma.rn.f32x2 %0, %1, %2, %0;" : "+l"(acc[p]) : "l"(xa.y), "l"(w1));
            asm("fma.rn.f32x2 %0, %1, %2, %0;" : "+l"(acc[p]) : "l"(xb.x), "l"(w2));
            asm("fma.rn.f32x2 %0, %1, %2, %0;" : "+l"(acc[p]) : "l"(xb.y), "l"(w3));
        }
    }

#pragma unroll
    for (int p = 0; p < 8; p++) {
        float lo, hi;
        asm("mov.b64 {%0, %1}, %2;" : "=f"(lo), "=f"(hi) : "l"(acc[p]));
        int n0 = row0 + 2 * (pbase + p), n1 = n0 + 1;
        if (which_w == 0) {
            lo = fmaxf(lo, 0.0f); hi = fmaxf(hi, 0.0f);
            if (n0 < N_NODES) g_h16b[n0 * HIDDEN + col] = __float2half(lo);
            if (n1 < N_NODES) g_h16b[n1 * HIDDEN + col] = __float2half(hi);
        } else {
            if (n0 < N_NODES) g_h[n0 * HIDDEN + col] = lo;
            if (n1 < N_NODES) g_h[n1 * HIDDEN + col] = hi;
        }
    }
}

// fused segmented mean-pool + classifier head: one block per graph
__global__ void __launch_bounds__(128) k_poolfinal(const float* __restrict__ Wl,
                                                   const float* __restrict__ bl,
                                                   float* __restrict__ out) {
    __shared__ float ps[HIDDEN];
    int g = blockIdx.x;
    int t = threadIdx.x;
    int s = g_gstart[g], e = g_gstart[g + 1];
    float acc = 0.0f;
    for (int n = s; n < e; n++)
        acc += g_h[n * HIDDEN + t];
    ps[t] = acc / fmaxf((float)(e - s), 1.0f);
    __syncthreads();
    if (t < NUM_CLASSES) {
        float o = bl[t];
#pragma unroll 8
        for (int h = 0; h < HIDDEN; h++)
            o += ps[h] * Wl[h * NUM_CLASSES + t];
        out[g * NUM_CLASSES + t] = o;
    }
}

// ---------------------------------------------------------------------------
extern "C" void kernel_launch(void* const* d_in, const int* in_sizes, int n_in,
                              void* d_out, int out_size) {
    const float* x     = (const float*)d_in[0];
    const int*   ei    = (const int*)d_in[1];
    const int*   batch = (const int*)d_in[2];
    const float* W1 = (const float*)d_in[3];
    const float* b1 = (const float*)d_in[4];
    const float* W2 = (const float*)d_in[5];
    const float* b2 = (const float*)d_in[6];
    const float* W3 = (const float*)d_in[7];
    const float* b3 = (const float*)d_in[8];
    const float* Wl = (const float*)d_in[9];
    const float* bl = (const float*)d_in[10];
    float* out = (float*)d_out;

    k_zero<<<(N_NODES + 255) / 256, 256>>>();                       // 1
    k_deg<<<(N_EDGES + 255) / 256, 256>>>(ei);                      // 2
    k_node_setup<<<(N_NODES + 255) / 256, 256>>>(batch, W2, W3);    // 3
    k_scan_lb<<<N_SBLK + 1, SCAN_B>>>();                            // 4
    k_scatter<<<(N_EDGES + 255) / 256, 256>>>(ei);                  // 5
    k_layer1<<<(N_NODES + 31) / 32, 128>>>(x, W1, b1);              // 6  <- profiled
    k_layer23<<<(N_NODES + 31) / 32, 256>>>(b2, 0);                 // 7
    k_layer23<<<(N_NODES + 31) / 32, 256>>>(b3, 1);                 // 8
    k_poolfinal<<<NUM_GRAPHS, 128>>>(Wl, bl, out);                  // 9
}

// round 11
// speedup vs baseline: 1.1342x; 1.1342x over previous
#include <cuda_runtime.h>
#include <cuda_fp16.h>

#define N_NODES     50000
#define N_EDGES     800000
#define HIDDEN      128
#define F_IN        11
#define NUM_CLASSES 19
#define NUM_GRAPHS  2048

#define SCAN_B      256
#define N_SBLK      ((N_NODES + SCAN_B - 1) / SCAN_B)   // 196

// ---- scratch ----
__device__ __align__(16) __half g_h16[N_NODES * HIDDEN];  // fp16 h (layers 1,2)
__device__ __align__(16) float g_h[N_NODES * HIDDEN];     // fp32 h (layer 3 out)
__device__ __align__(16) float g_agg[N_NODES * HIDDEN];
__device__ __align__(16) float g_agg11[N_NODES * 12];
__device__ float g_dinv[N_NODES];
__device__ int   g_counts[N_NODES];
__device__ int   g_fill[N_NODES];
__device__ int   g_rowptr[N_NODES + 1];
__device__ unsigned long long g_desc[N_SBLK];             // lookback descriptors
__device__ __align__(16) int2 g_edge[N_EDGES];            // (col, norm bits)
__device__ __align__(16) float g_Wt2[HIDDEN * HIDDEN];
__device__ __align__(16) float g_Wt3[HIDDEN * HIDDEN];
__device__ int   g_gcnt[NUM_GRAPHS];
__device__ int   g_gstart[NUM_GRAPHS + 1];

__device__ __forceinline__ int clampi(int v, int hi) {
    return v < 0 ? 0 : (v >= hi ? hi - 1 : v);
}

__device__ __forceinline__ void fma_h2(float4& acc, uint2 v, float w) {
    float2 fa = __half22float2(*(const __half2*)&v.x);
    float2 fb = __half22float2(*(const __half2*)&v.y);
    acc.x += w * fa.x; acc.y += w * fa.y; acc.z += w * fb.x; acc.w += w * fb.y;
}

// ---------------------------------------------------------------------------
__global__ void k_zero() {
    int i = blockIdx.x * blockDim.x + threadIdx.x;
    if (i < N_NODES) { g_counts[i] = 0; g_fill[i] = 0; }
    if (i < NUM_GRAPHS) g_gcnt[i] = 0;
    if (i < N_SBLK) g_desc[i] = 0ULL;
}

__global__ void k_deg(const int* __restrict__ ei) {
    int e = blockIdx.x * blockDim.x + threadIdx.x;
    if (e < N_EDGES) atomicAdd(&g_counts[clampi(ei[N_EDGES + e], N_NODES)], 1);
}

// fused: dinv + per-graph node counts + W2/W3 transpose
__global__ void k_node_setup(const int* __restrict__ batch,
                             const float* __restrict__ W2,
                             const float* __restrict__ W3) {
    int i = blockIdx.x * blockDim.x + threadIdx.x;
    if (i < N_NODES) {
        g_dinv[i] = rsqrtf((float)g_counts[i] + 1.0f);
        atomicAdd(&g_gcnt[clampi(batch[i], NUM_GRAPHS)], 1);
    }
    if (i < HIDDEN * HIDDEN) {
        int k = i / HIDDEN, c = i % HIDDEN;
        g_Wt2[c * HIDDEN + k] = W2[i];
        g_Wt3[c * HIDDEN + k] = W3[i];
    }
}

// single-pass scan: blocks 0..N_SBLK-1 decoupled-lookback scan of g_counts
// -> g_rowptr; block N_SBLK scans g_gcnt -> g_gstart.
__global__ void __launch_bounds__(SCAN_B) k_scan_lb() {
    __shared__ int s[SCAN_B];
    __shared__ unsigned int s_excl;
    int b = blockIdx.x;
    int t = threadIdx.x;
    volatile unsigned long long* vdesc = g_desc;

    if (b < N_SBLK) {
        int i = b * SCAN_B + t;
        int c = (i < N_NODES) ? g_counts[i] : 0;
        s[t] = c;
        __syncthreads();
        for (int off = 1; off < SCAN_B; off <<= 1) {
            int v = (t >= off) ? s[t - off] : 0;
            __syncthreads();
            s[t] += v;
            __syncthreads();
        }
        unsigned int total = (unsigned int)s[SCAN_B - 1];

        if (t < 32) {   // warp 0: publish + lookback
            if (b == 0) {
                if (t == 0) {
                    __threadfence();
                    vdesc[0] = (2ULL << 62) | (unsigned long long)total;
                    s_excl = 0;
                }
            } else {
                if (t == 0) {
                    __threadfence();
                    vdesc[b] = (1ULL << 62) | (unsigned long long)total;
                }
                unsigned long long sum = 0;
                int base = b - 1;
                while (true) {
                    int idx = base - t;
                    unsigned long long d = (idx >= 0) ? vdesc[idx] : (2ULL << 62);
                    unsigned st = (unsigned)(d >> 62);
                    unsigned long long val = d & 0xffffffffULL;
                    unsigned pmask = __ballot_sync(0xffffffff, st == 2);
                    unsigned zmask = __ballot_sync(0xffffffff, st == 0);
                    if (pmask) {
                        int fp = __ffs(pmask) - 1;
                        if (zmask & ((fp ? ((1u << fp) - 1u) : 0u))) continue;
                        unsigned long long con = (t <= fp) ? val : 0ULL;
                        for (int off = 16; off; off >>= 1)
                            con += __shfl_down_sync(0xffffffff, con, off);
                        if (t == 0) sum += con;
                        break;
                    } else {
                        if (zmask) continue;
                        unsigned long long con = val;
                        for (int off = 16; off; off >>= 1)
                            con += __shfl_down_sync(0xffffffff, con, off);
                        if (t == 0) sum += con;
                        base -= 32;
                    }
                }
                if (t == 0) {
                    __threadfence();
                    vdesc[b] = (2ULL << 62) | ((sum + total) & 0xffffffffULL);
                    s_excl = (unsigned int)sum;
                }
            }
        }
        __syncthreads();
        unsigned int excl = s_excl;
        if (i < N_NODES) g_rowptr[i] = (int)(excl + (unsigned int)s[t] - (unsigned int)c);
        if (i == N_NODES - 1) g_rowptr[N_NODES] = N_EDGES;
    } else {
        int base = t * 8;
        int vals[8];
        int th_total = 0;
#pragma unroll
        for (int j = 0; j < 8; j++) { vals[j] = g_gcnt[base + j]; th_total += vals[j]; }
        s[t] = th_total;
        __syncthreads();
        for (int off = 1; off < SCAN_B; off <<= 1) {
            int v = (t >= off) ? s[t - off] : 0;
            __syncthreads();
            s[t] += v;
            __syncthreads();
        }
        int run = s[t] - th_total;
#pragma unroll
        for (int j = 0; j < 8; j++) { g_gstart[base + j] = run; run += vals[j]; }
        if (t == SCAN_B - 1) g_gstart[NUM_GRAPHS] = s[SCAN_B - 1];
    }
}

__global__ void k_scatter(const int* __restrict__ ei) {
    int e = blockIdx.x * blockDim.x + threadIdx.x;
    if (e >= N_EDGES) return;
    int s = clampi(ei[e], N_NODES);
    int d = clampi(ei[N_EDGES + e], N_NODES);
    int pos = g_rowptr[d] + atomicAdd(&g_fill[d], 1);
    g_edge[pos] = make_int2(s, __float_as_int(g_dinv[s] * g_dinv[d]));
}

// aggregate raw x (11-dim): thread per (node, feature); 4-deep MLP pipeline
__global__ void k_agg11(const float* __restrict__ x) {
    int gid = blockIdx.x * blockDim.x + threadIdx.x;
    int node = gid >> 4;
    int f = gid & 15;
    if (node >= N_NODES || f >= F_IN) return;
    int s = g_rowptr[node], e = g_rowptr[node + 1];
    float acc = 0.0f;
    int i = s;
    for (; i + 4 <= e; i += 4) {
        int2 e0 = g_edge[i], e1 = g_edge[i + 1], e2 = g_edge[i + 2], e3 = g_edge[i + 3];
        float x0 = x[e0.x * F_IN + f];
        float x1 = x[e1.x * F_IN + f];
        float x2 = x[e2.x * F_IN + f];
        float x3 = x[e3.x * F_IN + f];
        acc += x0 * __int_as_float(e0.y) + x1 * __int_as_float(e1.y)
             + x2 * __int_as_float(e2.y) + x3 * __int_as_float(e3.y);
    }
    for (; i < e; i++) {
        int2 ed = g_edge[i];
        acc += x[ed.x * F_IN + f] * __int_as_float(ed.y);
    }
    float di = g_dinv[node];
    acc += x[node * F_IN + f] * (di * di);
    g_agg11[node * 12 + f] = acc;
}

// h1 = relu(agg11 @ W1 + b1) -> fp16
__global__ void k_gemm11(const float* __restrict__ W1, const float* __restrict__ b1) {
    __shared__ float Ws[F_IN * HIDDEN];
    __shared__ float xs[32][12];
    int t = threadIdx.x;
    int node0 = blockIdx.x * 32;
    for (int i = t; i < F_IN * HIDDEN; i += 128) Ws[i] = W1[i];
    for (int i = t; i < 32 * 12; i += 128) {
        int r = i / 12, f = i % 12;
        int n = node0 + r;
        xs[r][f] = (n < N_NODES) ? g_agg11[n * 12 + f] : 0.0f;
    }
    __syncthreads();
    float bb = b1[t];
    for (int n = 0; n < 32; n++) {
        int node = node0 + n;
        if (node >= N_NODES) break;
        float acc = bb;
#pragma unroll
        for (int k = 0; k < F_IN; k++)
            acc += xs[n][k] * Ws[k * HIDDEN + t];
        g_h16[node * HIDDEN + t] = __float2half(fmaxf(acc, 0.0f));
    }
}

// aggregate 128-dim fp16 features: warp per node, 4-deep MLP pipeline
__global__ void k_agg128() {
    int gid = blockIdx.x * blockDim.x + threadIdx.x;
    int node = gid >> 5;
    int lane = gid & 31;
    if (node >= N_NODES) return;
    int s = g_rowptr[node], e = g_rowptr[node + 1];
    const uint2* __restrict__ h2 = (const uint2*)g_h16;
    float4 acc = make_float4(0.f, 0.f, 0.f, 0.f);
    int i = s;
    for (; i + 4 <= e; i += 4) {
        int2 e0 = g_edge[i], e1 = g_edge[i + 1], e2 = g_edge[i + 2], e3 = g_edge[i + 3];
        uint2 v0 = h2[e0.x * 32 + lane];
        uint2 v1 = h2[e1.x * 32 + lane];
        uint2 v2 = h2[e2.x * 32 + lane];
        uint2 v3 = h2[e3.x * 32 + lane];
        fma_h2(acc, v0, __int_as_float(e0.y));
        fma_h2(acc, v1, __int_as_float(e1.y));
        fma_h2(acc, v2, __int_as_float(e2.y));
        fma_h2(acc, v3, __int_as_float(e3.y));
    }
    for (; i < e; i++) {
        int2 ed = g_edge[i];
        uint2 v = h2[ed.x * 32 + lane];
        fma_h2(acc, v, __int_as_float(ed.y));
    }
    float di = g_dinv[node];
    uint2 v = h2[node * 32 + lane];
    fma_h2(acc, v, di * di);
    ((float4*)g_agg)[node * 32 + lane] = acc;
}

// h = [relu](agg @ W + b) via fma.rn.f32x2.
// which_w: 0 -> W2^T, relu, fp16 out; 1 -> W3^T, no relu, fp32 out.
__global__ void k_gemm128_f2(const float* __restrict__ b, int which_w) {
    __shared__ __align__(16) float2 xs2[16][HIDDEN];   // 16 KB
    const float* __restrict__ Wt = which_w ? g_Wt3 : g_Wt2;
    int col = threadIdx.x;
    int row0 = blockIdx.x * 32;

    for (int i = col; i < 512; i += 128) {
        int p = i >> 5, kk = i & 31;
        int n0 = row0 + 2 * p, n1 = n0 + 1;
        float4 a = (n0 < N_NODES) ? ((const float4*)g_agg)[n0 * 32 + kk]
                                  : make_float4(0.f, 0.f, 0.f, 0.f);
        float4 c = (n1 < N_NODES) ? ((const float4*)g_agg)[n1 * 32 + kk]
                                  : make_float4(0.f, 0.f, 0.f, 0.f);
        float4* dst = (float4*)&xs2[p][4 * kk];
        dst[0] = make_float4(a.x, c.x, a.y, c.y);
        dst[1] = make_float4(a.z, c.z, a.w, c.w);
    }
    __syncthreads();

    unsigned long long acc[16];
    float bb = b[col];
    unsigned long long bb2;
    asm("mov.b64 %0, {%1, %1};" : "=l"(bb2) : "f"(bb));
#pragma unroll
    for (int p = 0; p < 16; p++) acc[p] = bb2;

    const float4* __restrict__ wt4 = (const float4*)(Wt + col * HIDDEN);
    for (int kk = 0; kk < 32; kk++) {
        float4 w = wt4[kk];
        unsigned long long w0, w1, w2, w3;
        asm("mov.b64 %0, {%1, %1};" : "=l"(w0) : "f"(w.x));
        asm("mov.b64 %0, {%1, %1};" : "=l"(w1) : "f"(w.y));
        asm("mov.b64 %0, {%1, %1};" : "=l"(w2) : "f"(w.z));
        asm("mov.b64 %0, {%1, %1};" : "=l"(w3) : "f"(w.w));
#pragma unroll
        for (int p = 0; p < 16; p++) {
            ulonglong2 xa = *(const ulonglong2*)&xs2[p][4 * kk];
            ulonglong2 xb = *(const ulonglong2*)&xs2[p][4 * kk + 2];
            asm("fma.rn.f32x2 %0, %1, %2, %0;" : "+l"(acc[p]) : "l"(xa.x), "l"(w0));
            asm("fma.rn.f32x2 %0, %1, %2, %0;" : "+l"(acc[p]) : "l"(xa.y), "l"(w1));
            asm("fma.rn.f32x2 %0, %1, %2, %0;" : "+l"(acc[p]) : "l"(xb.x), "l"(w2));
            asm("fma.rn.f32x2 %0, %1, %2, %0;" : "+l"(acc[p]) : "l"(xb.y), "l"(w3));
        }
    }

#pragma unroll
    for (int p = 0; p < 16; p++) {
        float lo, hi;
        asm("mov.b64 {%0, %1}, %2;" : "=f"(lo), "=f"(hi) : "l"(acc[p]));
        int n0 = row0 + 2 * p, n1 = n0 + 1;
        if (which_w == 0) {
            lo = fmaxf(lo, 0.0f); hi = fmaxf(hi, 0.0f);
            if (n0 < N_NODES) g_h16[n0 * HIDDEN + col] = __float2half(lo);
            if (n1 < N_NODES) g_h16[n1 * HIDDEN + col] = __float2half(hi);
        } else {
            if (n0 < N_NODES) g_h[n0 * HIDDEN + col] = lo;
            if (n1 < N_NODES) g_h[n1 * HIDDEN + col] = hi;
        }
    }
}

// fused segmented mean-pool + classifier head: one block per graph
__global__ void __launch_bounds__(128) k_poolfinal(const float* __restrict__ Wl,
                                                   const float* __restrict__ bl,
                                                   float* __restrict__ out) {
    __shared__ float ps[HIDDEN];
    int g = blockIdx.x;
    int t = threadIdx.x;
    int s = g_gstart[g], e = g_gstart[g + 1];
    float acc = 0.0f;
    for (int n = s; n < e; n++)
        acc += g_h[n * HIDDEN + t];
    ps[t] = acc / fmaxf((float)(e - s), 1.0f);
    __syncthreads();
    if (t < NUM_CLASSES) {
        float o = bl[t];
#pragma unroll 8
        for (int h = 0; h < HIDDEN; h++)
            o += ps[h] * Wl[h * NUM_CLASSES + t];
        out[g * NUM_CLASSES + t] = o;
    }
}

// ---------------------------------------------------------------------------
extern "C" void kernel_launch(void* const* d_in, const int* in_sizes, int n_in,
                              void* d_out, int out_size) {
    const float* x     = (const float*)d_in[0];
    const int*   ei    = (const int*)d_in[1];
    const int*   batch = (const int*)d_in[2];
    const float* W1 = (const float*)d_in[3];
    const float* b1 = (const float*)d_in[4];
    const float* W2 = (const float*)d_in[5];
    const float* b2 = (const float*)d_in[6];
    const float* W3 = (const float*)d_in[7];
    const float* b3 = (const float*)d_in[8];
    const float* Wl = (const float*)d_in[9];
    const float* bl = (const float*)d_in[10];
    float* out = (float*)d_out;

    k_zero<<<(N_NODES + 255) / 256, 256>>>();                       // 1
    k_deg<<<(N_EDGES + 255) / 256, 256>>>(ei);                      // 2
    k_node_setup<<<(N_NODES + 255) / 256, 256>>>(batch, W2, W3);    // 3
    k_scan_lb<<<N_SBLK + 1, SCAN_B>>>();                            // 4
    k_scatter<<<(N_EDGES + 255) / 256, 256>>>(ei);                  // 5
    k_agg11<<<(N_NODES * 16 + 255) / 256, 256>>>(x);                // 6
    k_gemm11<<<(N_NODES + 31) / 32, 128>>>(W1, b1);                 // 7
    k_agg128<<<(N_NODES * 32 + 255) / 256, 256>>>();                // 8
    k_gemm128_f2<<<(N_NODES + 31) / 32, 128>>>(b2, 0);              // 9
    k_agg128<<<(N_NODES * 32 + 255) / 256, 256>>>();                // 10
    k_gemm128_f2<<<(N_NODES + 31) / 32, 128>>>(b3, 1);              // 11
    k_poolfinal<<<NUM_GRAPHS, 128>>>(Wl, bl, out);                  // 12
}

// round 12
// speedup vs baseline: 1.2181x; 1.0740x over previous
#include <cuda_runtime.h>
#include <cuda_fp16.h>

#define N_NODES     50000
#define N_EDGES     800000
#define HIDDEN      128
#define F_IN        11
#define NUM_CLASSES 19
#define NUM_GRAPHS  2048

#define SCAN_B      256
#define N_SBLK      ((N_NODES + SCAN_B - 1) / SCAN_B)   // 196

// ---- scratch ----
__device__ __align__(16) __half g_h16[N_NODES * HIDDEN];  // fp16 h' = dinv*h (layers 1,2)
__device__ __align__(16) float g_h[N_NODES * HIDDEN];     // fp32 h (layer 3, unscaled)
__device__ __align__(16) float g_agg[N_NODES * HIDDEN];
__device__ __align__(16) float g_agg11[N_NODES * 12];
__device__ __align__(16) float g_x11s[N_NODES * 12];      // x' = dinv*x, padded
__device__ float g_dinv[N_NODES];
__device__ int   g_counts[N_NODES];
__device__ int   g_fill[N_NODES];
__device__ int   g_rowptr[N_NODES + 1];
__device__ unsigned long long g_desc[N_SBLK];
__device__ int   g_col[N_EDGES];                          // 4B/edge — no norm stored
__device__ __align__(16) float g_Wt2[HIDDEN * HIDDEN];
__device__ __align__(16) float g_Wt3[HIDDEN * HIDDEN];
__device__ int   g_gcnt[NUM_GRAPHS];
__device__ int   g_gstart[NUM_GRAPHS + 1];

__device__ __forceinline__ int clampi(int v, int hi) {
    return v < 0 ? 0 : (v >= hi ? hi - 1 : v);
}

__device__ __forceinline__ void add_h2(float4& acc, uint2 v) {
    float2 fa = __half22float2(*(const __half2*)&v.x);
    float2 fb = __half22float2(*(const __half2*)&v.y);
    acc.x += fa.x; acc.y += fa.y; acc.z += fb.x; acc.w += fb.y;
}

// ---------------------------------------------------------------------------
__global__ void k_zero() {
    int i = blockIdx.x * blockDim.x + threadIdx.x;
    if (i < N_NODES) { g_counts[i] = 0; g_fill[i] = 0; }
    if (i < NUM_GRAPHS) g_gcnt[i] = 0;
    if (i < N_SBLK) g_desc[i] = 0ULL;
}

__global__ void k_deg(const int* __restrict__ ei) {
    int e = blockIdx.x * blockDim.x + threadIdx.x;
    if (e < N_EDGES) atomicAdd(&g_counts[clampi(ei[N_EDGES + e], N_NODES)], 1);
}

// fused: dinv + x pre-scale + per-graph counts + W2/W3 transpose
__global__ void k_node_setup(const int* __restrict__ batch,
                             const float* __restrict__ x,
                             const float* __restrict__ W2,
                             const float* __restrict__ W3) {
    int i = blockIdx.x * blockDim.x + threadIdx.x;
    if (i < N_NODES) {
        float di = rsqrtf((float)g_counts[i] + 1.0f);
        g_dinv[i] = di;
        atomicAdd(&g_gcnt[clampi(batch[i], NUM_GRAPHS)], 1);
#pragma unroll
        for (int f = 0; f < F_IN; f++)
            g_x11s[i * 12 + f] = x[i * F_IN + f] * di;
    }
    if (i < HIDDEN * HIDDEN) {
        int k = i / HIDDEN, c = i % HIDDEN;
        g_Wt2[c * HIDDEN + k] = W2[i];
        g_Wt3[c * HIDDEN + k] = W3[i];
    }
}

// single-pass scan: blocks 0..N_SBLK-1 decoupled-lookback scan of g_counts
// -> g_rowptr; block N_SBLK scans g_gcnt -> g_gstart.
__global__ void __launch_bounds__(SCAN_B) k_scan_lb() {
    __shared__ int s[SCAN_B];
    __shared__ unsigned int s_excl;
    int b = blockIdx.x;
    int t = threadIdx.x;
    volatile unsigned long long* vdesc = g_desc;

    if (b < N_SBLK) {
        int i = b * SCAN_B + t;
        int c = (i < N_NODES) ? g_counts[i] : 0;
        s[t] = c;
        __syncthreads();
        for (int off = 1; off < SCAN_B; off <<= 1) {
            int v = (t >= off) ? s[t - off] : 0;
            __syncthreads();
            s[t] += v;
            __syncthreads();
        }
        unsigned int total = (unsigned int)s[SCAN_B - 1];

        if (t < 32) {
            if (b == 0) {
                if (t == 0) {
                    __threadfence();
                    vdesc[0] = (2ULL << 62) | (unsigned long long)total;
                    s_excl = 0;
                }
            } else {
                if (t == 0) {
                    __threadfence();
                    vdesc[b] = (1ULL << 62) | (unsigned long long)total;
                }
                unsigned long long sum = 0;
                int base = b - 1;
                while (true) {
                    int idx = base - t;
                    unsigned long long d = (idx >= 0) ? vdesc[idx] : (2ULL << 62);
                    unsigned st = (unsigned)(d >> 62);
                    unsigned long long val = d & 0xffffffffULL;
                    unsigned pmask = __ballot_sync(0xffffffff, st == 2);
                    unsigned zmask = __ballot_sync(0xffffffff, st == 0);
                    if (pmask) {
                        int fp = __ffs(pmask) - 1;
                        if (zmask & ((fp ? ((1u << fp) - 1u) : 0u))) continue;
                        unsigned long long con = (t <= fp) ? val : 0ULL;
                        for (int off = 16; off; off >>= 1)
                            con += __shfl_down_sync(0xffffffff, con, off);
                        if (t == 0) sum += con;
                        break;
                    } else {
                        if (zmask) continue;
                        unsigned long long con = val;
                        for (int off = 16; off; off >>= 1)
                            con += __shfl_down_sync(0xffffffff, con, off);
                        if (t == 0) sum += con;
                        base -= 32;
                    }
                }
                if (t == 0) {
                    __threadfence();
                    vdesc[b] = (2ULL << 62) | ((sum + total) & 0xffffffffULL);
                    s_excl = (unsigned int)sum;
                }
            }
        }
        __syncthreads();
        unsigned int excl = s_excl;
        if (i < N_NODES) g_rowptr[i] = (int)(excl + (unsigned int)s[t] - (unsigned int)c);
        if (i == N_NODES - 1) g_rowptr[N_NODES] = N_EDGES;
    } else {
        int base = t * 8;
        int vals[8];
        int th_total = 0;
#pragma unroll
        for (int j = 0; j < 8; j++) { vals[j] = g_gcnt[base + j]; th_total += vals[j]; }
        s[t] = th_total;
        __syncthreads();
        for (int off = 1; off < SCAN_B; off <<= 1) {
            int v = (t >= off) ? s[t - off] : 0;
            __syncthreads();
            s[t] += v;
            __syncthreads();
        }
        int run = s[t] - th_total;
#pragma unroll
        for (int j = 0; j < 8; j++) { g_gstart[base + j] = run; run += vals[j]; }
        if (t == SCAN_B - 1) g_gstart[NUM_GRAPHS] = s[SCAN_B - 1];
    }
}

// scatter: col only — no norm, no dinv gathers
__global__ void k_scatter(const int* __restrict__ ei) {
    int e = blockIdx.x * blockDim.x + threadIdx.x;
    if (e >= N_EDGES) return;
    int s = clampi(ei[e], N_NODES);
    int d = clampi(ei[N_EDGES + e], N_NODES);
    int pos = g_rowptr[d] + atomicAdd(&g_fill[d], 1);
    g_col[pos] = s;
}

// aggregate pre-scaled x' (11-dim): agg[d] = dinv[d]*(sum x'[src] + x'[d])
__global__ void k_agg11() {
    int gid = blockIdx.x * blockDim.x + threadIdx.x;
    int node = gid >> 4;
    int f = gid & 15;
    if (node >= N_NODES || f >= F_IN) return;
    int s = g_rowptr[node], e = g_rowptr[node + 1];
    float acc = 0.0f;
    int i = s;
    for (; i + 4 <= e; i += 4) {
        int c0 = g_col[i], c1 = g_col[i + 1], c2 = g_col[i + 2], c3 = g_col[i + 3];
        acc += g_x11s[c0 * 12 + f] + g_x11s[c1 * 12 + f]
             + g_x11s[c2 * 12 + f] + g_x11s[c3 * 12 + f];
    }
    for (; i < e; i++)
        acc += g_x11s[g_col[i] * 12 + f];
    acc += g_x11s[node * 12 + f];
    g_agg11[node * 12 + f] = acc * g_dinv[node];
}

// h1' = dinv * relu(agg11 @ W1 + b1) -> fp16
__global__ void k_gemm11(const float* __restrict__ W1, const float* __restrict__ b1) {
    __shared__ float Ws[F_IN * HIDDEN];
    __shared__ float xs[32][12];
    __shared__ float sdinv[32];
    int t = threadIdx.x;
    int node0 = blockIdx.x * 32;
    for (int i = t; i < F_IN * HIDDEN; i += 128) Ws[i] = W1[i];
    for (int i = t; i < 32 * 12; i += 128) {
        int r = i / 12, f = i % 12;
        int n = node0 + r;
        xs[r][f] = (n < N_NODES) ? g_agg11[n * 12 + f] : 0.0f;
    }
    if (t < 32) sdinv[t] = (node0 + t < N_NODES) ? g_dinv[node0 + t] : 1.0f;
    __syncthreads();
    float bb = b1[t];
    for (int n = 0; n < 32; n++) {
        int node = node0 + n;
        if (node >= N_NODES) break;
        float acc = bb;
#pragma unroll
        for (int k = 0; k < F_IN; k++)
            acc += xs[n][k] * Ws[k * HIDDEN + t];
        g_h16[node * HIDDEN + t] = __float2half(fmaxf(acc, 0.0f) * sdinv[n]);
    }
}

// aggregate 128-dim pre-scaled fp16 h': warp per node, 4-deep MLP pipeline
// out = dinv[node] * (sum h'[src] + h'[node])
__global__ void k_agg128() {
    int gid = blockIdx.x * blockDim.x + threadIdx.x;
    int node = gid >> 5;
    int lane = gid & 31;
    if (node >= N_NODES) return;
    int s = g_rowptr[node], e = g_rowptr[node + 1];
    const uint2* __restrict__ h2 = (const uint2*)g_h16;
    float4 acc = make_float4(0.f, 0.f, 0.f, 0.f);
    int i = s;
    for (; i + 4 <= e; i += 4) {
        int c0 = g_col[i], c1 = g_col[i + 1], c2 = g_col[i + 2], c3 = g_col[i + 3];
        uint2 v0 = h2[c0 * 32 + lane];
        uint2 v1 = h2[c1 * 32 + lane];
        uint2 v2 = h2[c2 * 32 + lane];
        uint2 v3 = h2[c3 * 32 + lane];
        add_h2(acc, v0); add_h2(acc, v1); add_h2(acc, v2); add_h2(acc, v3);
    }
    for (; i < e; i++)
        add_h2(acc, h2[g_col[i] * 32 + lane]);
    add_h2(acc, h2[node * 32 + lane]);
    float di = g_dinv[node];
    acc.x *= di; acc.y *= di; acc.z *= di; acc.w *= di;
    ((float4*)g_agg)[node * 32 + lane] = acc;
}

// h = [relu](agg @ W + b) via FFMA2; each thread computes 2 columns to halve LDS.
// which_w: 0 -> W2^T, relu, write h' = dinv*relu -> fp16; 1 -> W3^T, raw fp32 out.
__global__ void __launch_bounds__(128) k_gemm128_f2(const float* __restrict__ b, int which_w) {
    __shared__ __align__(16) float2 xs2[16][HIDDEN];   // 16 KB
    __shared__ float sdinv[32];
    const float* __restrict__ Wt = which_w ? g_Wt3 : g_Wt2;
    int t = threadIdx.x;
    int row0 = blockIdx.x * 32;

    for (int i = t; i < 512; i += 128) {
        int p = i >> 5, kk = i & 31;
        int n0 = row0 + 2 * p, n1 = n0 + 1;
        float4 a = (n0 < N_NODES) ? ((const float4*)g_agg)[n0 * 32 + kk]
                                  : make_float4(0.f, 0.f, 0.f, 0.f);
        float4 c = (n1 < N_NODES) ? ((const float4*)g_agg)[n1 * 32 + kk]
                                  : make_float4(0.f, 0.f, 0.f, 0.f);
        float4* dst = (float4*)&xs2[p][4 * kk];
        dst[0] = make_float4(a.x, c.x, a.y, c.y);
        dst[1] = make_float4(a.z, c.z, a.w, c.w);
    }
    if (t < 32) sdinv[t] = (row0 + t < N_NODES) ? g_dinv[row0 + t] : 1.0f;
    __syncthreads();

    int c0 = t & 63;           // first column
    int c1 = c0 + 64;          // second column
    int pbase = (t >> 6) * 8;  // 8 row-pairs per thread

    unsigned long long acc0[8], acc1[8];
    float bb0 = b[c0], bb1 = b[c1];
    unsigned long long bb0d, bb1d;
    asm("mov.b64 %0, {%1, %1};" : "=l"(bb0d) : "f"(bb0));
    asm("mov.b64 %0, {%1, %1};" : "=l"(bb1d) : "f"(bb1));
#pragma unroll
    for (int p = 0; p < 8; p++) { acc0[p] = bb0d; acc1[p] = bb1d; }

    const float4* __restrict__ wa4 = (const float4*)(Wt + c0 * HIDDEN);
    const float4* __restrict__ wb4 = (const float4*)(Wt + c1 * HIDDEN);
    for (int kk = 0; kk < 32; kk++) {
        float4 wa = wa4[kk];
        float4 wb = wb4[kk];
        unsigned long long a0, a1, a2, a3, b0, b1d, b2, b3;
        asm("mov.b64 %0, {%1, %1};" : "=l"(a0) : "f"(wa.x));
        asm("mov.b64 %0, {%1, %1};" : "=l"(a1) : "f"(wa.y));
        asm("mov.b64 %0, {%1, %1};" : "=l"(a2) : "f"(wa.z));
        asm("mov.b64 %0, {%1, %1};" : "=l"(a3) : "f"(wa.w));
        asm("mov.b64 %0, {%1, %1};" : "=l"(b0) : "f"(wb.x));
        asm("mov.b64 %0, {%1, %1};" : "=l"(b1d) : "f"(wb.y));
        asm("mov.b64 %0, {%1, %1};" : "=l"(b2) : "f"(wb.z));
        asm("mov.b64 %0, {%1, %1};" : "=l"(b3) : "f"(wb.w));
#pragma unroll
        for (int p = 0; p < 8; p++) {
            ulonglong2 xa = *(const ulonglong2*)&xs2[pbase + p][4 * kk];
            ulonglong2 xb = *(const ulonglong2*)&xs2[pbase + p][4 * kk + 2];
            asm("fma.rn.f32x2 %0, %1, %2, %0;" : "+l"(acc0[p]) : "l"(xa.x), "l"(a0));
            asm("fma.rn.f32x2 %0, %1, %2, %0;" : "+l"(acc1[p]) : "l"(xa.x), "l"(b0));
            asm("fma.rn.f32x2 %0, %1, %2, %0;" : "+l"(acc0[p]) : "l"(xa.y), "l"(a1));
            asm("fma.rn.f32x2 %0, %1, %2, %0;" : "+l"(acc1[p]) : "l"(xa.y), "l"(b1d));
            asm("fma.rn.f32x2 %0, %1, %2, %0;" : "+l"(acc0[p]) : "l"(xb.x), "l"(a2));
            asm("fma.rn.f32x2 %0, %1, %2, %0;" : "+l"(acc1[p]) : "l"(xb.x), "l"(b2));
            asm("fma.rn.f32x2 %0, %1, %2, %0;" : "+l"(acc0[p]) : "l"(xb.y), "l"(a3));
            asm("fma.rn.f32x2 %0, %1, %2, %0;" : "+l"(acc1[p]) : "l"(xb.y), "l"(b3));
        }
    }

#pragma unroll
    for (int p = 0; p < 8; p++) {
        int pr = pbase + p;
        int n0 = row0 + 2 * pr, n1 = n0 + 1;
        float lo0, hi0, lo1, hi1;
        asm("mov.b64 {%0, %1}, %2;" : "=f"(lo0), "=f"(hi0) : "l"(acc0[p]));
        asm("mov.b64 {%0, %1}, %2;" : "=f"(lo1), "=f"(hi1) : "l"(acc1[p]));
        if (which_w == 0) {
            float d0 = sdinv[2 * pr], d1 = sdinv[2 * pr + 1];
            lo0 = fmaxf(lo0, 0.0f) * d0; hi0 = fmaxf(hi0, 0.0f) * d1;
            lo1 = fmaxf(lo1, 0.0f) * d0; hi1 = fmaxf(hi1, 0.0f) * d1;
            if (n0 < N_NODES) {
                g_h16[n0 * HIDDEN + c0] = __float2half(lo0);
                g_h16[n0 * HIDDEN + c1] = __float2half(lo1);
            }
            if (n1 < N_NODES) {
                g_h16[n1 * HIDDEN + c0] = __float2half(hi0);
                g_h16[n1 * HIDDEN + c1] = __float2half(hi1);
            }
        } else {
            if (n0 < N_NODES) {
                g_h[n0 * HIDDEN + c0] = lo0;
                g_h[n0 * HIDDEN + c1] = lo1;
            }
            if (n1 < N_NODES) {
                g_h[n1 * HIDDEN + c0] = hi0;
                g_h[n1 * HIDDEN + c1] = hi1;
            }
        }
    }
}

// fused segmented mean-pool + classifier head: one block per graph
__global__ void __launch_bounds__(128) k_poolfinal(const float* __restrict__ Wl,
                                                   const float* __restrict__ bl,
                                                   float* __restrict__ out) {
    __shared__ float ps[HIDDEN];
    int g = blockIdx.x;
    int t = threadIdx.x;
    int s = g_gstart[g], e = g_gstart[g + 1];
    float acc = 0.0f;
    for (int n = s; n < e; n++)
        acc += g_h[n * HIDDEN + t];
    ps[t] = acc / fmaxf((float)(e - s), 1.0f);
    __syncthreads();
    if (t < NUM_CLASSES) {
        float o = bl[t];
#pragma unroll 8
        for (int h = 0; h < HIDDEN; h++)
            o += ps[h] * Wl[h * NUM_CLASSES + t];
        out[g * NUM_CLASSES + t] = o;
    }
}

// ---------------------------------------------------------------------------
extern "C" void kernel_launch(void* const* d_in, const int* in_sizes, int n_in,
                              void* d_out, int out_size) {
    const float* x     = (const float*)d_in[0];
    const int*   ei    = (const int*)d_in[1];
    const int*   batch = (const int*)d_in[2];
    const float* W1 = (const float*)d_in[3];
    const float* b1 = (const float*)d_in[4];
    const float* W2 = (const float*)d_in[5];
    const float* b2 = (const float*)d_in[6];
    const float* W3 = (const float*)d_in[7];
    const float* b3 = (const float*)d_in[8];
    const float* Wl = (const float*)d_in[9];
    const float* bl = (const float*)d_in[10];
    float* out = (float*)d_out;

    k_zero<<<(N_NODES + 255) / 256, 256>>>();                           // 1
    k_deg<<<(N_EDGES + 255) / 256, 256>>>(ei);                          // 2
    k_node_setup<<<(N_NODES + 255) / 256, 256>>>(batch, x, W2, W3);     // 3
    k_scan_lb<<<N_SBLK + 1, SCAN_B>>>();                                // 4
    k_scatter<<<(N_EDGES + 255) / 256, 256>>>(ei);                      // 5
    k_agg11<<<(N_NODES * 16 + 255) / 256, 256>>>();                     // 6
    k_gemm11<<<(N_NODES + 31) / 32, 128>>>(W1, b1);                     // 7
    k_agg128<<<(N_NODES * 32 + 255) / 256, 256>>>();                    // 8
    k_gemm128_f2<<<(N_NODES + 31) / 32, 128>>>(b2, 0);                  // 9
    k_agg128<<<(N_NODES * 32 + 255) / 256, 256>>>();                    // 10
    k_gemm128_f2<<<(N_NODES + 31) / 32, 128>>>(b3, 1);                  // 11
    k_poolfinal<<<NUM_GRAPHS, 128>>>(Wl, bl, out);                      // 12
}

// round 13
// speedup vs baseline: 1.4739x; 1.2100x over previous
#include <cuda_runtime.h>
#include <cuda_fp16.h>
#include <mma.h>

using namespace nvcuda;

#define N_NODES     50000
#define N_PAD       50016                 // padded to 32-row multiple for wmma tiles
#define N_EDGES     800000
#define HIDDEN      128
#define F_IN        11
#define NUM_CLASSES 19
#define NUM_GRAPHS  2048

#define SCAN_B      256
#define N_SBLK      ((N_NODES + SCAN_B - 1) / SCAN_B)   // 196

// ---- scratch ----
__device__ __align__(16) __half g_h16[N_NODES * HIDDEN];   // fp16 h' = dinv*h (layers 1,2)
__device__ __align__(16) __half g_agg16[N_PAD * HIDDEN];   // fp16 aggregated features
__device__ __align__(16) float g_h[N_NODES * HIDDEN];      // fp32 h (layer 3, unscaled)
__device__ __align__(16) float g_agg11[N_NODES * 12];
__device__ __align__(16) float g_x11s[N_NODES * 12];       // x' = dinv*x, padded
__device__ float g_dinv[N_NODES];
__device__ int   g_counts[N_NODES];
__device__ int   g_fill[N_NODES];
__device__ int   g_rowptr[N_NODES + 1];
__device__ unsigned long long g_desc[N_SBLK];
__device__ int   g_col[N_EDGES];                           // 4B/edge
__device__ __align__(16) __half g_W2h[HIDDEN * HIDDEN];    // fp16 W2 [k][c]
__device__ __align__(16) __half g_W3h[HIDDEN * HIDDEN];    // fp16 W3 [k][c]
__device__ int   g_gcnt[NUM_GRAPHS];
__device__ int   g_gstart[NUM_GRAPHS + 1];

__device__ __forceinline__ int clampi(int v, int hi) {
    return v < 0 ? 0 : (v >= hi ? hi - 1 : v);
}

__device__ __forceinline__ void add_h2(float4& acc, uint2 v) {
    float2 fa = __half22float2(*(const __half2*)&v.x);
    float2 fb = __half22float2(*(const __half2*)&v.y);
    acc.x += fa.x; acc.y += fa.y; acc.z += fb.x; acc.w += fb.y;
}

// ---------------------------------------------------------------------------
__global__ void k_zero() {
    int i = blockIdx.x * blockDim.x + threadIdx.x;
    if (i < N_NODES) { g_counts[i] = 0; g_fill[i] = 0; }
    if (i < NUM_GRAPHS) g_gcnt[i] = 0;
    if (i < N_SBLK) g_desc[i] = 0ULL;
}

__global__ void k_deg(const int* __restrict__ ei) {
    int e = blockIdx.x * blockDim.x + threadIdx.x;
    if (e < N_EDGES) atomicAdd(&g_counts[clampi(ei[N_EDGES + e], N_NODES)], 1);
}

// fused: dinv + x pre-scale + per-graph counts + W2/W3 fp16 convert
__global__ void k_node_setup(const int* __restrict__ batch,
                             const float* __restrict__ x,
                             const float* __restrict__ W2,
                             const float* __restrict__ W3) {
    int i = blockIdx.x * blockDim.x + threadIdx.x;
    if (i < N_NODES) {
        float di = rsqrtf((float)g_counts[i] + 1.0f);
        g_dinv[i] = di;
        atomicAdd(&g_gcnt[clampi(batch[i], NUM_GRAPHS)], 1);
#pragma unroll
        for (int f = 0; f < F_IN; f++)
            g_x11s[i * 12 + f] = x[i * F_IN + f] * di;
    }
    if (i < HIDDEN * HIDDEN) {
        g_W2h[i] = __float2half(W2[i]);
        g_W3h[i] = __float2half(W3[i]);
    }
}

// single-pass scan: blocks 0..N_SBLK-1 decoupled-lookback scan of g_counts
// -> g_rowptr; block N_SBLK scans g_gcnt -> g_gstart.
__global__ void __launch_bounds__(SCAN_B) k_scan_lb() {
    __shared__ int s[SCAN_B];
    __shared__ unsigned int s_excl;
    int b = blockIdx.x;
    int t = threadIdx.x;
    volatile unsigned long long* vdesc = g_desc;

    if (b < N_SBLK) {
        int i = b * SCAN_B + t;
        int c = (i < N_NODES) ? g_counts[i] : 0;
        s[t] = c;
        __syncthreads();
        for (int off = 1; off < SCAN_B; off <<= 1) {
            int v = (t >= off) ? s[t - off] : 0;
            __syncthreads();
            s[t] += v;
            __syncthreads();
        }
        unsigned int total = (unsigned int)s[SCAN_B - 1];

        if (t < 32) {
            if (b == 0) {
                if (t == 0) {
                    __threadfence();
                    vdesc[0] = (2ULL << 62) | (unsigned long long)total;
                    s_excl = 0;
                }
            } else {
                if (t == 0) {
                    __threadfence();
                    vdesc[b] = (1ULL << 62) | (unsigned long long)total;
                }
                unsigned long long sum = 0;
                int base = b - 1;
                while (true) {
                    int idx = base - t;
                    unsigned long long d = (idx >= 0) ? vdesc[idx] : (2ULL << 62);
                    unsigned st = (unsigned)(d >> 62);
                    unsigned long long val = d & 0xffffffffULL;
                    unsigned pmask = __ballot_sync(0xffffffff, st == 2);
                    unsigned zmask = __ballot_sync(0xffffffff, st == 0);
                    if (pmask) {
                        int fp = __ffs(pmask) - 1;
                        if (zmask & ((fp ? ((1u << fp) - 1u) : 0u))) continue;
                        unsigned long long con = (t <= fp) ? val : 0ULL;
                        for (int off = 16; off; off >>= 1)
                            con += __shfl_down_sync(0xffffffff, con, off);
                        if (t == 0) sum += con;
                        break;
                    } else {
                        if (zmask) continue;
                        unsigned long long con = val;
                        for (int off = 16; off; off >>= 1)
                            con += __shfl_down_sync(0xffffffff, con, off);
                        if (t == 0) sum += con;
                        base -= 32;
                    }
                }
                if (t == 0) {
                    __threadfence();
                    vdesc[b] = (2ULL << 62) | ((sum + total) & 0xffffffffULL);
                    s_excl = (unsigned int)sum;
                }
            }
        }
        __syncthreads();
        unsigned int excl = s_excl;
        if (i < N_NODES) g_rowptr[i] = (int)(excl + (unsigned int)s[t] - (unsigned int)c);
        if (i == N_NODES - 1) g_rowptr[N_NODES] = N_EDGES;
    } else {
        int base = t * 8;
        int vals[8];
        int th_total = 0;
#pragma unroll
        for (int j = 0; j < 8; j++) { vals[j] = g_gcnt[base + j]; th_total += vals[j]; }
        s[t] = th_total;
        __syncthreads();
        for (int off = 1; off < SCAN_B; off <<= 1) {
            int v = (t >= off) ? s[t - off] : 0;
            __syncthreads();
            s[t] += v;
            __syncthreads();
        }
        int run = s[t] - th_total;
#pragma unroll
        for (int j = 0; j < 8; j++) { g_gstart[base + j] = run; run += vals[j]; }
        if (t == SCAN_B - 1) g_gstart[NUM_GRAPHS] = s[SCAN_B - 1];
    }
}

// scatter: col only
__global__ void k_scatter(const int* __restrict__ ei) {
    int e = blockIdx.x * blockDim.x + threadIdx.x;
    if (e >= N_EDGES) return;
    int s = clampi(ei[e], N_NODES);
    int d = clampi(ei[N_EDGES + e], N_NODES);
    int pos = g_rowptr[d] + atomicAdd(&g_fill[d], 1);
    g_col[pos] = s;
}

// aggregate pre-scaled x' (11-dim): agg[d] = dinv[d]*(sum x'[src] + x'[d])
__global__ void k_agg11() {
    int gid = blockIdx.x * blockDim.x + threadIdx.x;
    int node = gid >> 4;
    int f = gid & 15;
    if (node >= N_NODES || f >= F_IN) return;
    int s = g_rowptr[node], e = g_rowptr[node + 1];
    float acc = 0.0f;
    int i = s;
    for (; i + 4 <= e; i += 4) {
        int c0 = g_col[i], c1 = g_col[i + 1], c2 = g_col[i + 2], c3 = g_col[i + 3];
        acc += g_x11s[c0 * 12 + f] + g_x11s[c1 * 12 + f]
             + g_x11s[c2 * 12 + f] + g_x11s[c3 * 12 + f];
    }
    for (; i < e; i++)
        acc += g_x11s[g_col[i] * 12 + f];
    acc += g_x11s[node * 12 + f];
    g_agg11[node * 12 + f] = acc * g_dinv[node];
}

// h1' = dinv * relu(agg11 @ W1 + b1) -> fp16
__global__ void k_gemm11(const float* __restrict__ W1, const float* __restrict__ b1) {
    __shared__ float Ws[F_IN * HIDDEN];
    __shared__ float xs[32][12];
    __shared__ float sdinv[32];
    int t = threadIdx.x;
    int node0 = blockIdx.x * 32;
    for (int i = t; i < F_IN * HIDDEN; i += 128) Ws[i] = W1[i];
    for (int i = t; i < 32 * 12; i += 128) {
        int r = i / 12, f = i % 12;
        int n = node0 + r;
        xs[r][f] = (n < N_NODES) ? g_agg11[n * 12 + f] : 0.0f;
    }
    if (t < 32) sdinv[t] = (node0 + t < N_NODES) ? g_dinv[node0 + t] : 1.0f;
    __syncthreads();
    float bb = b1[t];
    for (int n = 0; n < 32; n++) {
        int node = node0 + n;
        if (node >= N_NODES) break;
        float acc = bb;
#pragma unroll
        for (int k = 0; k < F_IN; k++)
            acc += xs[n][k] * Ws[k * HIDDEN + t];
        g_h16[node * HIDDEN + t] = __float2half(fmaxf(acc, 0.0f) * sdinv[n]);
    }
}

// aggregate 128-dim pre-scaled fp16 h': warp per node, 4-deep MLP pipeline
// out (fp16) = dinv[node] * (sum h'[src] + h'[node])
__global__ void k_agg128() {
    int gid = blockIdx.x * blockDim.x + threadIdx.x;
    int node = gid >> 5;
    int lane = gid & 31;
    if (node >= N_NODES) return;
    int s = g_rowptr[node], e = g_rowptr[node + 1];
    const uint2* __restrict__ h2 = (const uint2*)g_h16;
    float4 acc = make_float4(0.f, 0.f, 0.f, 0.f);
    int i = s;
    for (; i + 4 <= e; i += 4) {
        int c0 = g_col[i], c1 = g_col[i + 1], c2 = g_col[i + 2], c3 = g_col[i + 3];
        uint2 v0 = h2[c0 * 32 + lane];
        uint2 v1 = h2[c1 * 32 + lane];
        uint2 v2 = h2[c2 * 32 + lane];
        uint2 v3 = h2[c3 * 32 + lane];
        add_h2(acc, v0); add_h2(acc, v1); add_h2(acc, v2); add_h2(acc, v3);
    }
    for (; i < e; i++)
        add_h2(acc, h2[g_col[i] * 32 + lane]);
    add_h2(acc, h2[node * 32 + lane]);
    float di = g_dinv[node];
    __half2 p = __floats2half2_rn(acc.x * di, acc.y * di);
    __half2 q = __floats2half2_rn(acc.z * di, acc.w * di);
    uint2 o;
    o.x = *(unsigned int*)&p;
    o.y = *(unsigned int*)&q;
    ((uint2*)g_agg16)[node * 32 + lane] = o;
}

// tensor-core GEMM: C[32x128] = agg16[32x128] @ W16[128x128] (+bias, epilogue)
// which_w: 0 -> W2, relu, write h' = dinv*relu -> fp16; 1 -> W3, raw fp32 out.
__global__ void __launch_bounds__(256) k_gemm_wmma(const float* __restrict__ b, int which_w) {
    __shared__ float Cs[32][132];      // 132 = 128 + 4 pad
    __shared__ float sdinv[32];
    __shared__ float sb[HIDDEN];
    const __half* __restrict__ W16 = which_w ? g_W3h : g_W2h;
    int t = threadIdx.x;
    int wid = t >> 5;
    int wr = wid >> 2;                 // warp row 0..1  (16 rows each)
    int wc = wid & 3;                  // warp col 0..3  (32 cols each)
    int row0 = blockIdx.x * 32;

    if (t < 32) sdinv[t] = (row0 + t < N_NODES) ? g_dinv[row0 + t] : 1.0f;
    if (t < HIDDEN) sb[t] = b[t];

    wmma::fragment<wmma::accumulator, 16, 16, 16, float> c0, c1;
    wmma::fill_fragment(c0, 0.0f);
    wmma::fill_fragment(c1, 0.0f);

    const __half* Abase = g_agg16 + (row0 + wr * 16) * HIDDEN;
#pragma unroll
    for (int k = 0; k < HIDDEN; k += 16) {
        wmma::fragment<wmma::matrix_a, 16, 16, 16, __half, wmma::row_major> af;
        wmma::load_matrix_sync(af, Abase + k, HIDDEN);
        wmma::fragment<wmma::matrix_b, 16, 16, 16, __half, wmma::row_major> b0f, b1f;
        wmma::load_matrix_sync(b0f, W16 + k * HIDDEN + wc * 32, HIDDEN);
        wmma::load_matrix_sync(b1f, W16 + k * HIDDEN + wc * 32 + 16, HIDDEN);
        wmma::mma_sync(c0, af, b0f, c0);
        wmma::mma_sync(c1, af, b1f, c1);
    }
    wmma::store_matrix_sync(&Cs[wr * 16][wc * 32], c0, 132, wmma::mem_row_major);
    wmma::store_matrix_sync(&Cs[wr * 16][wc * 32 + 16], c1, 132, wmma::mem_row_major);
    __syncthreads();

    // epilogue: 256 threads x 16 elems
    int r = t >> 3;
    int cb = (t & 7) * 16;
    int node = row0 + r;
    if (node < N_NODES) {
        if (which_w == 0) {
            float di = sdinv[r];
#pragma unroll
            for (int j = 0; j < 16; j++) {
                float v = Cs[r][cb + j] + sb[cb + j];
                g_h16[node * HIDDEN + cb + j] = __float2half(fmaxf(v, 0.0f) * di);
            }
        } else {
#pragma unroll
            for (int j = 0; j < 16; j++)
                g_h[node * HIDDEN + cb + j] = Cs[r][cb + j] + sb[cb + j];
        }
    }
}

// fused segmented mean-pool + classifier head: one block per graph
__global__ void __launch_bounds__(128) k_poolfinal(const float* __restrict__ Wl,
                                                   const float* __restrict__ bl,
                                                   float* __restrict__ out) {
    __shared__ float ps[HIDDEN];
    int g = blockIdx.x;
    int t = threadIdx.x;
    int s = g_gstart[g], e = g_gstart[g + 1];
    float acc = 0.0f;
    for (int n = s; n < e; n++)
        acc += g_h[n * HIDDEN + t];
    ps[t] = acc / fmaxf((float)(e - s), 1.0f);
    __syncthreads();
    if (t < NUM_CLASSES) {
        float o = bl[t];
#pragma unroll 8
        for (int h = 0; h < HIDDEN; h++)
            o += ps[h] * Wl[h * NUM_CLASSES + t];
        out[g * NUM_CLASSES + t] = o;
    }
}

// ---------------------------------------------------------------------------
extern "C" void kernel_launch(void* const* d_in, const int* in_sizes, int n_in,
                              void* d_out, int out_size) {
    const float* x     = (const float*)d_in[0];
    const int*   ei    = (const int*)d_in[1];
    const int*   batch = (const int*)d_in[2];
    const float* W1 = (const float*)d_in[3];
    const float* b1 = (const float*)d_in[4];
    const float* W2 = (const float*)d_in[5];
    const float* b2 = (const float*)d_in[6];
    const float* W3 = (const float*)d_in[7];
    const float* b3 = (const float*)d_in[8];
    const float* Wl = (const float*)d_in[9];
    const float* bl = (const float*)d_in[10];
    float* out = (float*)d_out;

    k_zero<<<(N_NODES + 255) / 256, 256>>>();                           // 1
    k_deg<<<(N_EDGES + 255) / 256, 256>>>(ei);                          // 2
    k_node_setup<<<(N_NODES + 255) / 256, 256>>>(batch, x, W2, W3);     // 3
    k_scan_lb<<<N_SBLK + 1, SCAN_B>>>();                                // 4
    k_scatter<<<(N_EDGES + 255) / 256, 256>>>(ei);                      // 5
    k_agg11<<<(N_NODES * 16 + 255) / 256, 256>>>();                     // 6
    k_gemm11<<<(N_NODES + 31) / 32, 128>>>(W1, b1);                     // 7
    k_agg128<<<(N_NODES * 32 + 255) / 256, 256>>>();                    // 8
    k_gemm_wmma<<<(N_NODES + 31) / 32, 256>>>(b2, 0);                   // 9
    k_agg128<<<(N_NODES * 32 + 255) / 256, 256>>>();                    // 10
    k_gemm_wmma<<<(N_NODES + 31) / 32, 256>>>(b3, 1);                   // 11
    k_poolfinal<<<NUM_GRAPHS, 128>>>(Wl, bl, out);                      // 12
}

// round 14
// speedup vs baseline: 1.5960x; 1.0828x over previous
#include <cuda_runtime.h>
#include <cuda_fp16.h>
#include <mma.h>

using namespace nvcuda;

#define N_NODES     50000
#define N_PAD       50016                 // padded to 32-row multiple for wmma tiles
#define N_EDGES     800000
#define HIDDEN      128
#define F_IN        11
#define NUM_CLASSES 19
#define NUM_GRAPHS  2048

#define SCAN_B      256
#define N_SBLK      ((N_NODES + SCAN_B - 1) / SCAN_B)   // 196

// ---- scratch ----
__device__ __align__(16) __half g_h16[N_NODES * HIDDEN];   // fp16 h' = dinv*h (layers 1,2)
__device__ __align__(16) __half g_agg16[N_PAD * HIDDEN];   // fp16 aggregated features
__device__ __align__(16) float g_agg11[N_NODES * 12];
__device__ __align__(16) float g_x11s[N_NODES * 12];       // x' = dinv*x, padded
__device__ float g_dinv[N_NODES];
__device__ int   g_counts[N_NODES];
__device__ int   g_fill[N_NODES];
__device__ int   g_rowptr[N_NODES + 1];
__device__ unsigned long long g_desc[N_SBLK];
__device__ int   g_col[N_EDGES];                           // 4B/edge
__device__ __align__(16) __half g_W2h[HIDDEN * HIDDEN];    // fp16 W2 [k][c]
__device__ __align__(16) __half g_W3h[HIDDEN * HIDDEN];    // fp16 W3 [k][c]
__device__ float g_pool[NUM_GRAPHS * HIDDEN];              // per-graph sums (layer 3)
__device__ int   g_gcnt[NUM_GRAPHS];

__device__ __forceinline__ int clampi(int v, int hi) {
    return v < 0 ? 0 : (v >= hi ? hi - 1 : v);
}

__device__ __forceinline__ void add_h2(float4& acc, uint2 v) {
    float2 fa = __half22float2(*(const __half2*)&v.x);
    float2 fb = __half22float2(*(const __half2*)&v.y);
    acc.x += fa.x; acc.y += fa.y; acc.z += fb.x; acc.w += fb.y;
}

// ---------------------------------------------------------------------------
__global__ void k_zero() {   // grid covers NUM_GRAPHS*HIDDEN = 262144
    int i = blockIdx.x * blockDim.x + threadIdx.x;
    if (i < NUM_GRAPHS * HIDDEN) g_pool[i] = 0.0f;
    if (i < N_NODES) { g_counts[i] = 0; g_fill[i] = 0; }
    if (i < NUM_GRAPHS) g_gcnt[i] = 0;
    if (i < N_SBLK) g_desc[i] = 0ULL;
}

__global__ void k_deg(const int* __restrict__ ei) {
    int e = blockIdx.x * blockDim.x + threadIdx.x;
    if (e < N_EDGES) atomicAdd(&g_counts[clampi(ei[N_EDGES + e], N_NODES)], 1);
}

// fused: dinv + x pre-scale + per-graph counts + W2/W3 fp16 convert
__global__ void k_node_setup(const int* __restrict__ batch,
                             const float* __restrict__ x,
                             const float* __restrict__ W2,
                             const float* __restrict__ W3) {
    int i = blockIdx.x * blockDim.x + threadIdx.x;
    if (i < N_NODES) {
        float di = rsqrtf((float)g_counts[i] + 1.0f);
        g_dinv[i] = di;
        atomicAdd(&g_gcnt[clampi(batch[i], NUM_GRAPHS)], 1);
#pragma unroll
        for (int f = 0; f < F_IN; f++)
            g_x11s[i * 12 + f] = x[i * F_IN + f] * di;
    }
    if (i < HIDDEN * HIDDEN) {
        g_W2h[i] = __float2half(W2[i]);
        g_W3h[i] = __float2half(W3[i]);
    }
}

// single-pass decoupled-lookback scan of g_counts -> g_rowptr
__global__ void __launch_bounds__(SCAN_B) k_scan_lb() {
    __shared__ int s[SCAN_B];
    __shared__ unsigned int s_excl;
    int b = blockIdx.x;
    int t = threadIdx.x;
    volatile unsigned long long* vdesc = g_desc;

    int i = b * SCAN_B + t;
    int c = (i < N_NODES) ? g_counts[i] : 0;
    s[t] = c;
    __syncthreads();
    for (int off = 1; off < SCAN_B; off <<= 1) {
        int v = (t >= off) ? s[t - off] : 0;
        __syncthreads();
        s[t] += v;
        __syncthreads();
    }
    unsigned int total = (unsigned int)s[SCAN_B - 1];

    if (t < 32) {
        if (b == 0) {
            if (t == 0) {
                __threadfence();
                vdesc[0] = (2ULL << 62) | (unsigned long long)total;
                s_excl = 0;
            }
        } else {
            if (t == 0) {
                __threadfence();
                vdesc[b] = (1ULL << 62) | (unsigned long long)total;
            }
            unsigned long long sum = 0;
            int base = b - 1;
            while (true) {
                int idx = base - t;
                unsigned long long d = (idx >= 0) ? vdesc[idx] : (2ULL << 62);
                unsigned st = (unsigned)(d >> 62);
                unsigned long long val = d & 0xffffffffULL;
                unsigned pmask = __ballot_sync(0xffffffff, st == 2);
                unsigned zmask = __ballot_sync(0xffffffff, st == 0);
                if (pmask) {
                    int fp = __ffs(pmask) - 1;
                    if (zmask & ((fp ? ((1u << fp) - 1u) : 0u))) continue;
                    unsigned long long con = (t <= fp) ? val : 0ULL;
                    for (int off = 16; off; off >>= 1)
                        con += __shfl_down_sync(0xffffffff, con, off);
                    if (t == 0) sum += con;
                    break;
                } else {
                    if (zmask) continue;
                    unsigned long long con = val;
                    for (int off = 16; off; off >>= 1)
                        con += __shfl_down_sync(0xffffffff, con, off);
                    if (t == 0) sum += con;
                    base -= 32;
                }
            }
            if (t == 0) {
                __threadfence();
                vdesc[b] = (2ULL << 62) | ((sum + total) & 0xffffffffULL);
                s_excl = (unsigned int)sum;
            }
        }
    }
    __syncthreads();
    unsigned int excl = s_excl;
    if (i < N_NODES) g_rowptr[i] = (int)(excl + (unsigned int)s[t] - (unsigned int)c);
    if (i == N_NODES - 1) g_rowptr[N_NODES] = N_EDGES;
}

// scatter: col only
__global__ void k_scatter(const int* __restrict__ ei) {
    int e = blockIdx.x * blockDim.x + threadIdx.x;
    if (e >= N_EDGES) return;
    int s = clampi(ei[e], N_NODES);
    int d = clampi(ei[N_EDGES + e], N_NODES);
    int pos = g_rowptr[d] + atomicAdd(&g_fill[d], 1);
    g_col[pos] = s;
}

// aggregate pre-scaled x' (11-dim): agg[d] = dinv[d]*(sum x'[src] + x'[d])
__global__ void k_agg11() {
    int gid = blockIdx.x * blockDim.x + threadIdx.x;
    int node = gid >> 4;
    int f = gid & 15;
    if (node >= N_NODES || f >= F_IN) return;
    int s = g_rowptr[node], e = g_rowptr[node + 1];
    float acc = 0.0f;
    int i = s;
    for (; i + 4 <= e; i += 4) {
        int c0 = g_col[i], c1 = g_col[i + 1], c2 = g_col[i + 2], c3 = g_col[i + 3];
        acc += g_x11s[c0 * 12 + f] + g_x11s[c1 * 12 + f]
             + g_x11s[c2 * 12 + f] + g_x11s[c3 * 12 + f];
    }
    for (; i < e; i++)
        acc += g_x11s[g_col[i] * 12 + f];
    acc += g_x11s[node * 12 + f];
    g_agg11[node * 12 + f] = acc * g_dinv[node];
}

// h1' = dinv * relu(agg11 @ W1 + b1) -> fp16
__global__ void k_gemm11(const float* __restrict__ W1, const float* __restrict__ b1) {
    __shared__ float Ws[F_IN * HIDDEN];
    __shared__ float xs[32][12];
    __shared__ float sdinv[32];
    int t = threadIdx.x;
    int node0 = blockIdx.x * 32;
    for (int i = t; i < F_IN * HIDDEN; i += 128) Ws[i] = W1[i];
    for (int i = t; i < 32 * 12; i += 128) {
        int r = i / 12, f = i % 12;
        int n = node0 + r;
        xs[r][f] = (n < N_NODES) ? g_agg11[n * 12 + f] : 0.0f;
    }
    if (t < 32) sdinv[t] = (node0 + t < N_NODES) ? g_dinv[node0 + t] : 1.0f;
    __syncthreads();
    float bb = b1[t];
    for (int n = 0; n < 32; n++) {
        int node = node0 + n;
        if (node >= N_NODES) break;
        float acc = bb;
#pragma unroll
        for (int k = 0; k < F_IN; k++)
            acc += xs[n][k] * Ws[k * HIDDEN + t];
        g_h16[node * HIDDEN + t] = __float2half(fmaxf(acc, 0.0f) * sdinv[n]);
    }
}

// aggregate 128-dim pre-scaled fp16 h': warp per node, 8-deep MLP pipeline
// out (fp16) = dinv[node] * (sum h'[src] + h'[node])
__global__ void k_agg128() {
    int gid = blockIdx.x * blockDim.x + threadIdx.x;
    int node = gid >> 5;
    int lane = gid & 31;
    if (node >= N_NODES) return;
    int s = g_rowptr[node], e = g_rowptr[node + 1];
    const uint2* __restrict__ h2 = (const uint2*)g_h16;
    float4 acc = make_float4(0.f, 0.f, 0.f, 0.f);
    int i = s;
    for (; i + 8 <= e; i += 8) {
        int c0 = g_col[i],     c1 = g_col[i + 1], c2 = g_col[i + 2], c3 = g_col[i + 3];
        int c4 = g_col[i + 4], c5 = g_col[i + 5], c6 = g_col[i + 6], c7 = g_col[i + 7];
        uint2 v0 = h2[c0 * 32 + lane];
        uint2 v1 = h2[c1 * 32 + lane];
        uint2 v2 = h2[c2 * 32 + lane];
        uint2 v3 = h2[c3 * 32 + lane];
        uint2 v4 = h2[c4 * 32 + lane];
        uint2 v5 = h2[c5 * 32 + lane];
        uint2 v6 = h2[c6 * 32 + lane];
        uint2 v7 = h2[c7 * 32 + lane];
        add_h2(acc, v0); add_h2(acc, v1); add_h2(acc, v2); add_h2(acc, v3);
        add_h2(acc, v4); add_h2(acc, v5); add_h2(acc, v6); add_h2(acc, v7);
    }
    for (; i + 4 <= e; i += 4) {
        int c0 = g_col[i], c1 = g_col[i + 1], c2 = g_col[i + 2], c3 = g_col[i + 3];
        uint2 v0 = h2[c0 * 32 + lane];
        uint2 v1 = h2[c1 * 32 + lane];
        uint2 v2 = h2[c2 * 32 + lane];
        uint2 v3 = h2[c3 * 32 + lane];
        add_h2(acc, v0); add_h2(acc, v1); add_h2(acc, v2); add_h2(acc, v3);
    }
    for (; i < e; i++)
        add_h2(acc, h2[g_col[i] * 32 + lane]);
    add_h2(acc, h2[node * 32 + lane]);
    float di = g_dinv[node];
    __half2 p = __floats2half2_rn(acc.x * di, acc.y * di);
    __half2 q = __floats2half2_rn(acc.z * di, acc.w * di);
    uint2 o;
    o.x = *(unsigned int*)&p;
    o.y = *(unsigned int*)&q;
    ((uint2*)g_agg16)[node * 32 + lane] = o;
}

// tensor-core GEMM: C[32x128] = agg16[32x128] @ W16[128x128] + bias
// which_w=0: W2, relu, write h' = dinv*relu -> fp16
// which_w=1: W3, accumulate per-graph sums into g_pool (no g_h roundtrip)
__global__ void __launch_bounds__(256) k_gemm_wmma(const float* __restrict__ b, int which_w,
                                                   const int* __restrict__ batch) {
    __shared__ float Cs[32][132];      // 132 = 128 + 4 pad
    __shared__ float sdinv[32];
    __shared__ float sb[HIDDEN];
    __shared__ int   sgid[32];
    const __half* __restrict__ W16 = which_w ? g_W3h : g_W2h;
    int t = threadIdx.x;
    int wid = t >> 5;
    int wr = wid >> 2;                 // warp row 0..1  (16 rows each)
    int wc = wid & 3;                  // warp col 0..3  (32 cols each)
    int row0 = blockIdx.x * 32;

    if (t < 32) {
        int node = row0 + t;
        sdinv[t] = (node < N_NODES) ? g_dinv[node] : 1.0f;
        sgid[t] = (node < N_NODES) ? clampi(batch[node], NUM_GRAPHS) : -1;
    }
    if (t < HIDDEN) sb[t] = b[t];

    wmma::fragment<wmma::accumulator, 16, 16, 16, float> c0, c1;
    wmma::fill_fragment(c0, 0.0f);
    wmma::fill_fragment(c1, 0.0f);

    const __half* Abase = g_agg16 + (row0 + wr * 16) * HIDDEN;
#pragma unroll
    for (int k = 0; k < HIDDEN; k += 16) {
        wmma::fragment<wmma::matrix_a, 16, 16, 16, __half, wmma::row_major> af;
        wmma::load_matrix_sync(af, Abase + k, HIDDEN);
        wmma::fragment<wmma::matrix_b, 16, 16, 16, __half, wmma::row_major> b0f, b1f;
        wmma::load_matrix_sync(b0f, W16 + k * HIDDEN + wc * 32, HIDDEN);
        wmma::load_matrix_sync(b1f, W16 + k * HIDDEN + wc * 32 + 16, HIDDEN);
        wmma::mma_sync(c0, af, b0f, c0);
        wmma::mma_sync(c1, af, b1f, c1);
    }
    wmma::store_matrix_sync(&Cs[wr * 16][wc * 32], c0, 132, wmma::mem_row_major);
    wmma::store_matrix_sync(&Cs[wr * 16][wc * 32 + 16], c1, 132, wmma::mem_row_major);
    __syncthreads();

    if (which_w == 0) {
        // epilogue: relu + dinv scale -> fp16 h'
        int r = t >> 3;
        int cb = (t & 7) * 16;
        int node = row0 + r;
        if (node < N_NODES) {
            float di = sdinv[r];
#pragma unroll
            for (int j = 0; j < 16; j++) {
                float v = Cs[r][cb + j] + sb[cb + j];
                g_h16[node * HIDDEN + cb + j] = __float2half(fmaxf(v, 0.0f) * di);
            }
        }
    } else {
        // epilogue: per-graph partial sums (batch sorted -> few graphs per block)
        int col = t & 127;
        int rbase = (t >> 7) * 16;
        float run = 0.0f;
        int cur = sgid[rbase];
#pragma unroll
        for (int j = 0; j < 16; j++) {
            int r = rbase + j;
            int g = sgid[r];
            if (g != cur) {
                if (cur >= 0) atomicAdd(&g_pool[cur * HIDDEN + col], run);
                run = 0.0f;
                cur = g;
            }
            if (g >= 0) run += Cs[r][col] + sb[col];
        }
        if (cur >= 0) atomicAdd(&g_pool[cur * HIDDEN + col], run);
    }
}

// final: mean + classifier head per graph
__global__ void __launch_bounds__(128) k_final(const float* __restrict__ Wl,
                                               const float* __restrict__ bl,
                                               float* __restrict__ out) {
    __shared__ float ps[HIDDEN];
    int g = blockIdx.x;
    int t = threadIdx.x;
    float inv = 1.0f / fmaxf((float)g_gcnt[g], 1.0f);
    ps[t] = g_pool[g * HIDDEN + t] * inv;
    __syncthreads();
    if (t < NUM_CLASSES) {
        float o = bl[t];
#pragma unroll 8
        for (int h = 0; h < HIDDEN; h++)
            o += ps[h] * Wl[h * NUM_CLASSES + t];
        out[g * NUM_CLASSES + t] = o;
    }
}

// ---------------------------------------------------------------------------
extern "C" void kernel_launch(void* const* d_in, const int* in_sizes, int n_in,
                              void* d_out, int out_size) {
    const float* x     = (const float*)d_in[0];
    const int*   ei    = (const int*)d_in[1];
    const int*   batch = (const int*)d_in[2];
    const float* W1 = (const float*)d_in[3];
    const float* b1 = (const float*)d_in[4];
    const float* W2 = (const float*)d_in[5];
    const float* b2 = (const float*)d_in[6];
    const float* W3 = (const float*)d_in[7];
    const float* b3 = (const float*)d_in[8];
    const float* Wl = (const float*)d_in[9];
    const float* bl = (const float*)d_in[10];
    float* out = (float*)d_out;

    const int ZN = NUM_GRAPHS * HIDDEN;   // 262144 — largest zero range
    k_zero<<<(ZN + 255) / 256, 256>>>();                                // 1
    k_deg<<<(N_EDGES + 255) / 256, 256>>>(ei);                          // 2
    k_scan_lb<<<N_SBLK, SCAN_B>>>();                                    // 3
    k_scatter<<<(N_EDGES + 255) / 256, 256>>>(ei);                      // 4  <- profiled slot
    k_node_setup<<<(N_NODES + 255) / 256, 256>>>(batch, x, W2, W3);     // 5
    k_agg11<<<(N_NODES * 16 + 255) / 256, 256>>>();                     // 6
    k_gemm11<<<(N_NODES + 31) / 32, 128>>>(W1, b1);                     // 7
    k_agg128<<<(N_NODES * 32 + 255) / 256, 256>>>();                    // 8
    k_gemm_wmma<<<(N_NODES + 31) / 32, 256>>>(b2, 0, batch);            // 9
    k_agg128<<<(N_NODES * 32 + 255) / 256, 256>>>();                    // 10
    k_gemm_wmma<<<(N_NODES + 31) / 32, 256>>>(b3, 1, batch);            // 11
    k_final<<<NUM_GRAPHS, 128>>>(Wl, bl, out);                          // 12
}